// round 2
// baseline (speedup 1.0000x reference)
#include <cuda_runtime.h>

#define NB 4
#define NN 4096
#define FIN 256
#define FOUT 128
#define ROWS (NB*NN)
#define NCH (NN/32)   // 128 mask chunks per row

// -------- scratch (static __device__, no allocs) --------
__device__ float    g_Wh[(size_t)ROWS*FOUT];     // 8 MB
__device__ float    g_Wh1[ROWS];
__device__ float    g_Wh2[ROWS];
__device__ float    g_invZ[ROWS];
__device__ unsigned g_mask[(size_t)ROWS*NCH];    // 8 MB packed adjacency

__device__ __forceinline__ unsigned long long fma2(unsigned long long a,
                                                   unsigned long long b,
                                                   unsigned long long c) {
    unsigned long long d;
    asm("fma.rn.f32x2 %0, %1, %2, %3;" : "=l"(d) : "l"(a), "l"(b), "l"(c));
    return d;
}

// ================= Kernel 1: Wh = h @ W  (fp32 tiled GEMM) =================
__global__ void __launch_bounds__(256) k_gemm(const float* __restrict__ h,
                                              const float* __restrict__ W) {
    __shared__ float As[64][32];
    __shared__ float Bs[32][FOUT];
    const int block_row = blockIdx.x * 64;
    const int tid = threadIdx.x;
    const int tx = tid & 31;   // col quad: cols 4*tx .. 4*tx+3
    const int ty = tid >> 5;   // row oct:  rows ty*8 .. ty*8+7

    float acc[8][4];
#pragma unroll
    for (int r = 0; r < 8; r++) { acc[r][0]=acc[r][1]=acc[r][2]=acc[r][3]=0.f; }

    for (int k0 = 0; k0 < FIN; k0 += 32) {
#pragma unroll
        for (int i = tid; i < 64*32; i += 256) {
            int r = i >> 5, c = i & 31;
            As[r][c] = h[(size_t)(block_row + r)*FIN + k0 + c];
        }
#pragma unroll
        for (int i = tid; i < 32*FOUT; i += 256) {
            int r = i >> 7, c = i & 127;
            Bs[r][c] = W[(size_t)(k0 + r)*FOUT + c];
        }
        __syncthreads();
#pragma unroll
        for (int kk = 0; kk < 32; kk++) {
            float4 bv = *(const float4*)&Bs[kk][tx*4];
#pragma unroll
            for (int r = 0; r < 8; r++) {
                float av = As[ty*8 + r][kk];
                acc[r][0] += av*bv.x; acc[r][1] += av*bv.y;
                acc[r][2] += av*bv.z; acc[r][3] += av*bv.w;
            }
        }
        __syncthreads();
    }
#pragma unroll
    for (int r = 0; r < 8; r++) {
        float4 v = make_float4(acc[r][0], acc[r][1], acc[r][2], acc[r][3]);
        *(float4*)&g_Wh[(size_t)(block_row + ty*8 + r)*FOUT + tx*4] = v;
    }
}

// ============ Kernel 2: Wh1 = Wh·a1, Wh2 = Wh·a2 (one warp per row) ========
__global__ void __launch_bounds__(256) k_rowvec(const float* __restrict__ a) {
    int warp = (blockIdx.x * blockDim.x + threadIdx.x) >> 5;
    int lane = threadIdx.x & 31;
    if (warp >= ROWS) return;
    const float* wr = g_Wh + (size_t)warp*FOUT;
    float s1 = 0.f, s2 = 0.f;
#pragma unroll
    for (int j = 0; j < 4; j++) {
        int o = lane + 32*j;
        float v = wr[o];
        s1 += v * a[o];
        s2 += v * a[FOUT + o];
    }
#pragma unroll
    for (int off = 16; off; off >>= 1) {
        s1 += __shfl_xor_sync(0xffffffffu, s1, off);
        s2 += __shfl_xor_sync(0xffffffffu, s2, off);
    }
    if (lane == 0) { g_Wh1[warp] = s1; g_Wh2[warp] = s2; }
}

// ==== Kernel 3: single pass over adj (256 MB): pack bits + softmax denom ===
// e in +/-~15, so exp(e) is fp32-safe without max subtraction -> one pass.
__global__ void __launch_bounds__(256) k_stats(const int* __restrict__ adj) {
    int warp = (blockIdx.x * blockDim.x + threadIdx.x) >> 5;
    int lane = threadIdx.x & 31;
    if (warp >= ROWS) return;
    const int row = warp;
    const int b = row >> 12;
    const float w1 = g_Wh1[row];
    const int*   arow = adj + (size_t)row * NN;
    const float* wh2b = g_Wh2 + (size_t)b * NN;
    float sum = 0.f;
#pragma unroll 4
    for (int c = 0; c < NCH; c++) {
        int m = c*32 + lane;
        int av = arow[m];
        float e = w1 + wh2b[m];
        e = (e >= 0.f) ? e : 0.2f*e;
        bool act = (av > 0);
        unsigned bal = __ballot_sync(0xffffffffu, act);
        if (act) sum += __expf(e);
        if (lane == 0) g_mask[(size_t)row*NCH + c] = bal;
    }
#pragma unroll
    for (int off = 16; off; off >>= 1) sum += __shfl_xor_sync(0xffffffffu, sum, off);
    if (lane == 0) g_invZ[row] = 1.f / sum;
}

// ============ Kernel 4: h' = attn @ Wh, then ELU (flash-style PV) ==========
// Block: 64 rows x 128 cols, 256 threads. Thread: 8 rows x 4 cols, packed
// f32x2 accumulators. attn recomputed from rank-1 scores + packed mask.
__global__ void __launch_bounds__(256) k_pv(float* __restrict__ out) {
    __shared__ float    Whs[32][FOUT];   // 16 KB  value tile
    __shared__ float    ps[64][32];      //  8 KB  attn tile
    __shared__ float    wh1s[64], invzs[64], wh2s[32];
    __shared__ unsigned ms[64];

    const int b   = blockIdx.y;
    const int n0  = blockIdx.x * 64;
    const int row0 = b*NN + n0;
    const int tid = threadIdx.x;
    const int tx = tid & 31;   // cols 4*tx..
    const int ty = tid >> 5;   // rows ty*8..

    if (tid < 64) { wh1s[tid] = g_Wh1[row0 + tid]; invzs[tid] = g_invZ[row0 + tid]; }

    unsigned long long acc[8][2];
#pragma unroll
    for (int r = 0; r < 8; r++) { acc[r][0] = 0ull; acc[r][1] = 0ull; }

    for (int m0 = 0; m0 < NN; m0 += 32) {
        __syncthreads();
        // ---- load tile of Wh (32 x 128) ----
        {
            const float4* src = (const float4*)(g_Wh + ((size_t)b*NN + m0)*FOUT);
            float4* dst = (float4*)&Whs[0][0];
#pragma unroll
            for (int i = 0; i < 4; i++) dst[tid + 256*i] = src[tid + 256*i];
        }
        if (tid < 64)       ms[tid]        = g_mask[(size_t)(row0 + tid)*NCH + (m0 >> 5)];
        else if (tid < 96)  wh2s[tid - 64] = g_Wh2[(size_t)b*NN + m0 + (tid - 64)];
        __syncthreads();
        // ---- compute attn tile p[64][32] ----
#pragma unroll
        for (int j = 0; j < 8; j++) {
            int idx = tid*8 + j;
            int r = idx >> 5, mm = idx & 31;
            float e = wh1s[r] + wh2s[mm];
            e = (e >= 0.f) ? e : 0.2f*e;
            float p = ((ms[r] >> mm) & 1u) ? __expf(e) * invzs[r] : 0.f;
            ps[r][mm] = p;
        }
        __syncthreads();
        // ---- accumulate: acc += p * Wh  (packed f32x2 FMA) ----
#pragma unroll 4
        for (int mm = 0; mm < 32; mm++) {
            ulonglong2 bb = *(const ulonglong2*)&Whs[mm][tx*4];
#pragma unroll
            for (int r = 0; r < 8; r++) {
                float p = ps[ty*8 + r][mm];
                unsigned long long p2;
                asm("mov.b64 %0, {%1, %1};" : "=l"(p2) : "r"(__float_as_uint(p)));
                acc[r][0] = fma2(p2, bb.x, acc[r][0]);
                acc[r][1] = fma2(p2, bb.y, acc[r][1]);
            }
        }
    }
    // ---- epilogue: unpack, ELU, store ----
#pragma unroll
    for (int r = 0; r < 8; r++) {
        int row = row0 + ty*8 + r;
        float v0 = __uint_as_float((unsigned)(acc[r][0] & 0xffffffffull));
        float v1 = __uint_as_float((unsigned)(acc[r][0] >> 32));
        float v2 = __uint_as_float((unsigned)(acc[r][1] & 0xffffffffull));
        float v3 = __uint_as_float((unsigned)(acc[r][1] >> 32));
        v0 = (v0 > 0.f) ? v0 : expm1f(v0);
        v1 = (v1 > 0.f) ? v1 : expm1f(v1);
        v2 = (v2 > 0.f) ? v2 : expm1f(v2);
        v3 = (v3 > 0.f) ? v3 : expm1f(v3);
        *(float4*)&out[(size_t)row*FOUT + tx*4] = make_float4(v0, v1, v2, v3);
    }
}

extern "C" void kernel_launch(void* const* d_in, const int* in_sizes, int n_in,
                              void* d_out, int out_size) {
    const float* h   = (const float*)d_in[0];
    const int*   adj = (const int*)  d_in[1];
    const float* W   = (const float*)d_in[2];
    const float* a   = (const float*)d_in[3];
    float* out = (float*)d_out;

    k_gemm  <<<ROWS/64, 256>>>(h, W);
    k_rowvec<<<ROWS/8,  256>>>(a);
    k_stats <<<ROWS/8,  256>>>(adj);
    dim3 g(NN/64, NB);
    k_pv    <<<g, 256>>>(out);
}

// round 4
// speedup vs baseline: 1.5010x; 1.5010x over previous
#include <cuda_runtime.h>
#include <cstdint>

#define NB 4
#define NN 4096
#define FIN 256
#define FOUT 128
#define ROWS (NB*NN)
#define NCH 128            // 4096/32 k-chunks
#define PSTR 40            // padded smem row stride (words) == 8 mod 32 -> conflict-free LDS.64

// -------- scratch (static __device__, no allocs) --------
__device__ float    g_Wh[(size_t)ROWS*FOUT];            // 8 MB   Wh row-major [row][f]
__device__ float    g_WhB[(size_t)NB*FOUT*NN];          // 8 MB   [b][n][k] tf32, k-pair-permuted per 8
__device__ float    g_Wh1[ROWS];
__device__ float    g_Wh2[ROWS];
__device__ float    g_invZ[ROWS];
__device__ unsigned g_maskT[(size_t)NB*NCH*NN];         // 8 MB   [b][chunk][n] packed adjacency

__device__ __forceinline__ float to_tf32(float x) {
    uint32_t b; asm("cvt.rna.tf32.f32 %0, %1;" : "=r"(b) : "f"(x));
    return __uint_as_float(b);
}
__device__ __forceinline__ void mma_tf32(float* d, uint32_t a0, uint32_t a1, uint32_t a2, uint32_t a3,
                                         uint32_t b0, uint32_t b1) {
    asm volatile("mma.sync.aligned.m16n8k8.row.col.f32.tf32.tf32.f32 "
                 "{%0,%1,%2,%3}, {%4,%5,%6,%7}, {%8,%9}, {%0,%1,%2,%3};"
                 : "+f"(d[0]), "+f"(d[1]), "+f"(d[2]), "+f"(d[3])
                 : "r"(a0), "r"(a1), "r"(a2), "r"(a3), "r"(b0), "r"(b1));
}

// ================= Kernel 1: Wh = h @ W  (fp32 tiled GEMM) =================
__global__ void __launch_bounds__(256) k_gemm(const float* __restrict__ h,
                                              const float* __restrict__ W) {
    __shared__ float As[64][32];
    __shared__ float Bsm[32][FOUT];
    const int block_row = blockIdx.x * 64;
    const int tid = threadIdx.x;
    const int tx = tid & 31, ty = tid >> 5;
    float acc[8][4];
#pragma unroll
    for (int r = 0; r < 8; r++) { acc[r][0]=acc[r][1]=acc[r][2]=acc[r][3]=0.f; }
    for (int k0 = 0; k0 < FIN; k0 += 32) {
#pragma unroll
        for (int i = tid; i < 64*32; i += 256) {
            int r = i >> 5, c = i & 31;
            As[r][c] = h[(size_t)(block_row + r)*FIN + k0 + c];
        }
#pragma unroll
        for (int i = tid; i < 32*FOUT; i += 256) {
            int r = i >> 7, c = i & 127;
            Bsm[r][c] = W[(size_t)(k0 + r)*FOUT + c];
        }
        __syncthreads();
#pragma unroll
        for (int kk = 0; kk < 32; kk++) {
            float4 bv = *(const float4*)&Bsm[kk][tx*4];
#pragma unroll
            for (int r = 0; r < 8; r++) {
                float av = As[ty*8 + r][kk];
                acc[r][0] += av*bv.x; acc[r][1] += av*bv.y;
                acc[r][2] += av*bv.z; acc[r][3] += av*bv.w;
            }
        }
        __syncthreads();
    }
#pragma unroll
    for (int r = 0; r < 8; r++) {
        *(float4*)&g_Wh[(size_t)(block_row + ty*8 + r)*FOUT + tx*4] =
            make_float4(acc[r][0], acc[r][1], acc[r][2], acc[r][3]);
    }
}

// ============ Kernel 2: Wh1 = Wh·a1, Wh2 = Wh·a2 ============
__global__ void __launch_bounds__(256) k_rowvec(const float* __restrict__ a) {
    int warp = (blockIdx.x * blockDim.x + threadIdx.x) >> 5;
    int lane = threadIdx.x & 31;
    if (warp >= ROWS) return;
    const float* wr = g_Wh + (size_t)warp*FOUT;
    float s1 = 0.f, s2 = 0.f;
#pragma unroll
    for (int j = 0; j < 4; j++) {
        int o = lane + 32*j;
        float v = wr[o];
        s1 += v * a[o];
        s2 += v * a[FOUT + o];
    }
#pragma unroll
    for (int off = 16; off; off >>= 1) {
        s1 += __shfl_xor_sync(0xffffffffu, s1, off);
        s2 += __shfl_xor_sync(0xffffffffu, s2, off);
    }
    if (lane == 0) { g_Wh1[warp] = s1; g_Wh2[warp] = s2; }
}

// ==== Kernel 3: Wh -> WhB [b][n][k] tf32, K pair-permuted: within each 8-k
// group, pos = 8s + 2t holds k=8s+t, pos+1 holds k=8s+t+4 (so b0,b1 = one LDS.64)
__global__ void __launch_bounds__(128) k_trans() {
    __shared__ float ts[32*128];
    const int c = blockIdx.x, b = blockIdx.y, tid = threadIdx.x;
    const float4* src = (const float4*)(g_Wh + ((size_t)(b*NN + c*32))*FOUT);
    float4* td = (float4*)ts;
#pragma unroll
    for (int i = 0; i < 8; i++) td[tid + 128*i] = src[tid + 128*i];
    __syncthreads();
    const int n = tid;
    float* dst = g_WhB + ((size_t)b*FOUT + n)*NN + c*32;
#pragma unroll
    for (int s = 0; s < 4; s++)
#pragma unroll
        for (int t = 0; t < 4; t++) {
            float2 v;
            v.x = to_tf32(ts[(s*8 + t    )*128 + n]);
            v.y = to_tf32(ts[(s*8 + t + 4)*128 + n]);
            *(float2*)(dst + s*8 + 2*t) = v;
        }
}

// ==== Kernel 4: single pass over adj: pack bits (transposed) + softmax denom ====
__global__ void __launch_bounds__(256) k_stats(const int* __restrict__ adj) {
    int warp = (blockIdx.x * blockDim.x + threadIdx.x) >> 5;
    int lane = threadIdx.x & 31;
    if (warp >= ROWS) return;
    const int row = warp, b = row >> 12, n = row & (NN-1);
    const float w1 = g_Wh1[row];
    const int*   arow = adj + (size_t)row * NN;
    const float* wh2b = g_Wh2 + (size_t)b * NN;
    float sum = 0.f;
    for (int c = 0; c < 32; c++) {
        int base = c*128 + lane;
        int a0 = arow[base], a1 = arow[base+32], a2 = arow[base+64], a3 = arow[base+96];
        float e0 = w1 + wh2b[base],    e1 = w1 + wh2b[base+32];
        float e2 = w1 + wh2b[base+64], e3 = w1 + wh2b[base+96];
        e0 = (e0>=0.f)?e0:0.2f*e0; e1 = (e1>=0.f)?e1:0.2f*e1;
        e2 = (e2>=0.f)?e2:0.2f*e2; e3 = (e3>=0.f)?e3:0.2f*e3;
        unsigned b0 = __ballot_sync(0xffffffffu, a0>0);
        unsigned b1 = __ballot_sync(0xffffffffu, a1>0);
        unsigned b2 = __ballot_sync(0xffffffffu, a2>0);
        unsigned b3 = __ballot_sync(0xffffffffu, a3>0);
        if (a0>0) sum += __expf(e0);
        if (a1>0) sum += __expf(e1);
        if (a2>0) sum += __expf(e2);
        if (a3>0) sum += __expf(e3);
        if (lane == 0) {
            g_maskT[((size_t)(b*NCH) + c*4 + 0)*NN + n] = b0;
            g_maskT[((size_t)(b*NCH) + c*4 + 1)*NN + n] = b1;
            g_maskT[((size_t)(b*NCH) + c*4 + 2)*NN + n] = b2;
            g_maskT[((size_t)(b*NCH) + c*4 + 3)*NN + n] = b3;
        }
    }
#pragma unroll
    for (int off = 16; off; off >>= 1) sum += __shfl_xor_sync(0xffffffffu, sum, off);
    if (lane == 0) g_invZ[row] = 1.f / sum;
}

// ============ Kernel 5: h' = attn @ Wh via mma.sync tf32, then ELU ============
// CTA 128M x 128N, 8 warps (4M x 2N), warp tile 32x64. K chunks of 32.
__global__ void __launch_bounds__(256) k_pv(float* __restrict__ out) {
    __shared__ float Ps[128*PSTR];     // 20 KB  P tile (k pair-permuted cols)
    __shared__ float Ws[128*PSTR];     // 20 KB  Wh^T tile
    __shared__ float wh2s[NN];         // 16 KB

    const int b   = blockIdx.y;
    const int n0  = blockIdx.x * 128;
    const int tid = threadIdx.x;
    const int warp = tid >> 5, lane = tid & 31;
    const int g = lane >> 2, t = lane & 3;
    const int mband = (warp >> 1) * 32;      // 4 M-warps
    const int nband = (warp & 1) * 64;       // 2 N-warps

    // P-producer role: thread -> row mrow_p, k-half
    const int mrow_p = tid >> 1;
    const int khalf  = (tid & 1) * 16;       // k offset (2 of 4 s-groups)
    const float w1 = g_Wh1[b*NN + n0 + mrow_p];
    const float iz = g_invZ[b*NN + n0 + mrow_p];

    // cache wh2 for this batch
    {
        const float4* s4 = (const float4*)(g_Wh2 + (size_t)b*NN);
        float4* d4 = (float4*)wh2s;
#pragma unroll
        for (int i = 0; i < 4; i++) d4[tid + 256*i] = s4[tid + 256*i];
    }

    // W staging role: thread -> row nrow_w, k-half (16 floats = 2 float4)
    const int nrow_w = tid >> 1;
    const float* gW = g_WhB + ((size_t)b*FOUT + nrow_w)*NN + khalf;
    float4 w0 = *(const float4*)(gW + 0);
    float4 w1r = *(const float4*)(gW + 4);
    float4 w2r = *(const float4*)(gW + 8);
    float4 w3r = *(const float4*)(gW + 12);

    float acc[2][8][4];
#pragma unroll
    for (int mf = 0; mf < 2; mf++)
#pragma unroll
        for (int nf = 0; nf < 8; nf++)
#pragma unroll
            for (int i = 0; i < 4; i++) acc[mf][nf][i] = 0.f;

    __syncthreads();

    for (int c = 0; c < NCH; c++) {
        // stage W tile from prefetch regs (layout already permuted in gmem)
        float* wd = &Ws[nrow_w*PSTR + khalf];
        *(float4*)(wd + 0) = w0;  *(float4*)(wd + 4) = w1r;
        *(float4*)(wd + 8) = w2r; *(float4*)(wd + 12) = w3r;

        // compute P row-slice (16 vals) -> smem (pair-permuted)
        {
            const unsigned mw = g_maskT[((size_t)(b*NCH) + c)*NN + n0 + mrow_p];
            const float* w2c = wh2s + c*32;
            float* pd = &Ps[mrow_p*PSTR];
#pragma unroll
            for (int sl = 0; sl < 2; sl++) {
                int s = (khalf >> 3) + sl;
#pragma unroll
                for (int tt = 0; tt < 4; tt++) {
                    int k0 = s*8 + tt, k1 = k0 + 4;
                    float e0 = w1 + w2c[k0]; e0 = (e0>=0.f)?e0:0.2f*e0;
                    float e1 = w1 + w2c[k1]; e1 = (e1>=0.f)?e1:0.2f*e1;
                    float p0 = ((mw >> k0) & 1u) ? __expf(e0)*iz : 0.f;
                    float p1 = ((mw >> k1) & 1u) ? __expf(e1)*iz : 0.f;
                    float2 v; v.x = to_tf32(p0); v.y = to_tf32(p1);
                    *(float2*)(pd + s*8 + 2*tt) = v;
                }
            }
        }
        // prefetch next W chunk
        if (c + 1 < NCH) {
            const float* gn = gW + (c + 1)*32 - khalf + khalf; // base advances by chunk
            const float* gp = g_WhB + ((size_t)b*FOUT + nrow_w)*NN + (c+1)*32 + khalf;
            w0 = *(const float4*)(gp + 0);  w1r = *(const float4*)(gp + 4);
            w2r = *(const float4*)(gp + 8); w3r = *(const float4*)(gp + 12);
            (void)gn;
        }
        __syncthreads();

        // MMA: 4 k-steps of 8
#pragma unroll
        for (int ks = 0; ks < 4; ks++) {
            uint2 bf[8];
#pragma unroll
            for (int nf = 0; nf < 8; nf++)
                bf[nf] = *(const uint2*)&Ws[(nband + nf*8 + g)*PSTR + ks*8 + 2*t];
#pragma unroll
            for (int mf = 0; mf < 2; mf++) {
                uint2 aLo = *(const uint2*)&Ps[(mband + mf*16 + g    )*PSTR + ks*8 + 2*t]; // a0,a2
                uint2 aHi = *(const uint2*)&Ps[(mband + mf*16 + g + 8)*PSTR + ks*8 + 2*t]; // a1,a3
#pragma unroll
                for (int nf = 0; nf < 8; nf++)
                    mma_tf32(acc[mf][nf], aLo.x, aHi.x, aLo.y, aHi.y, bf[nf].x, bf[nf].y);
            }
        }
        __syncthreads();
    }

    // epilogue: ELU + store
#pragma unroll
    for (int mf = 0; mf < 2; mf++) {
        int r0 = b*NN + n0 + mband + mf*16 + g;
#pragma unroll
        for (int nf = 0; nf < 8; nf++) {
            int col = nband + nf*8 + t*2;
            float d0 = acc[mf][nf][0], d1 = acc[mf][nf][1];
            float d2 = acc[mf][nf][2], d3 = acc[mf][nf][3];
            d0 = (d0 > 0.f) ? d0 : expm1f(d0);
            d1 = (d1 > 0.f) ? d1 : expm1f(d1);
            d2 = (d2 > 0.f) ? d2 : expm1f(d2);
            d3 = (d3 > 0.f) ? d3 : expm1f(d3);
            *(float2*)&out[(size_t)r0*FOUT + col]       = make_float2(d0, d1);
            *(float2*)&out[(size_t)(r0+8)*FOUT + col]   = make_float2(d2, d3);
        }
    }
}

extern "C" void kernel_launch(void* const* d_in, const int* in_sizes, int n_in,
                              void* d_out, int out_size) {
    const float* h   = (const float*)d_in[0];
    const int*   adj = (const int*)  d_in[1];
    const float* W   = (const float*)d_in[2];
    const float* a   = (const float*)d_in[3];
    float* out = (float*)d_out;

    k_gemm  <<<ROWS/64, 256>>>(h, W);
    k_rowvec<<<ROWS/8,  256>>>(a);
    { dim3 g(NCH, NB); k_trans<<<g, 128>>>(); }
    k_stats <<<ROWS/8,  256>>>(adj);
    { dim3 g(NN/128, NB); k_pv<<<g, 256>>>(out); }
}

// round 5
// speedup vs baseline: 2.0824x; 1.3873x over previous
#include <cuda_runtime.h>
#include <cstdint>

#define NB 4
#define NN 4096
#define FIN 256
#define FOUT 128
#define ROWS (NB*NN)
#define NCH 128            // 4096/32 k-chunks
#define PSTR 40            // smem row stride (words); 40 mod 32 = 8 -> conflict-free LDS.64

// -------- scratch (static __device__, no allocs) --------
__device__ float    g_Wh[(size_t)ROWS*FOUT];            // 8 MB   Wh row-major [row][f]
__device__ float    g_WhB[(size_t)NB*FOUT*NN];          // 8 MB   [b][f][k-pos] tf32 (pi-ordered, pair-permuted)
__device__ float    g_Wh1[ROWS];
__device__ float    g_Wh2[ROWS];
__device__ float    g_Wh2p[NB*NN];                      // Wh2 in pi order
__device__ float    g_invZ[ROWS];
__device__ unsigned g_maskT[(size_t)NB*NCH*NN];         // 8 MB   [b][chunk][n], bit l <-> m = pi(chunk,l)

// pi(c, l) = (c>>2)*128 + 4*l + (c&3)   -- matches int4-ballot order in k_stats

__device__ __forceinline__ float to_tf32(float x) {
    uint32_t b; asm("cvt.rna.tf32.f32 %0, %1;" : "=r"(b) : "f"(x));
    return __uint_as_float(b);
}
__device__ __forceinline__ void mma_tf32(float* d, uint32_t a0, uint32_t a1, uint32_t a2, uint32_t a3,
                                         uint32_t b0, uint32_t b1) {
    asm volatile("mma.sync.aligned.m16n8k8.row.col.f32.tf32.tf32.f32 "
                 "{%0,%1,%2,%3}, {%4,%5,%6,%7}, {%8,%9}, {%0,%1,%2,%3};"
                 : "+f"(d[0]), "+f"(d[1]), "+f"(d[2]), "+f"(d[3])
                 : "r"(a0), "r"(a1), "r"(a2), "r"(a3), "r"(b0), "r"(b1));
}
__device__ __forceinline__ uint32_t smem_u32(const void* p) {
    uint32_t a;
    asm("{ .reg .u64 t; cvta.to.shared.u64 t, %1; cvt.u32.u64 %0, t; }" : "=r"(a) : "l"(p));
    return a;
}
__device__ __forceinline__ void cp_async16(uint32_t dst, const void* src) {
    asm volatile("cp.async.ca.shared.global [%0], [%1], 16;" :: "r"(dst), "l"(src));
}
#define CP_COMMIT() asm volatile("cp.async.commit_group;" ::: "memory")
#define CP_WAIT1()  asm volatile("cp.async.wait_group 1;" ::: "memory")

// ================= Kernel 1: Wh = h @ W  (fp32 tiled GEMM) =================
__global__ void __launch_bounds__(256) k_gemm(const float* __restrict__ h,
                                              const float* __restrict__ W) {
    __shared__ float As[64][32];
    __shared__ float Bsm[32][FOUT];
    const int block_row = blockIdx.x * 64;
    const int tid = threadIdx.x;
    const int tx = tid & 31, ty = tid >> 5;
    float acc[8][4];
#pragma unroll
    for (int r = 0; r < 8; r++) { acc[r][0]=acc[r][1]=acc[r][2]=acc[r][3]=0.f; }
    for (int k0 = 0; k0 < FIN; k0 += 32) {
#pragma unroll
        for (int i = tid; i < 64*32; i += 256) {
            int r = i >> 5, c = i & 31;
            As[r][c] = h[(size_t)(block_row + r)*FIN + k0 + c];
        }
#pragma unroll
        for (int i = tid; i < 32*FOUT; i += 256) {
            int r = i >> 7, c = i & 127;
            Bsm[r][c] = W[(size_t)(k0 + r)*FOUT + c];
        }
        __syncthreads();
#pragma unroll
        for (int kk = 0; kk < 32; kk++) {
            float4 bv = *(const float4*)&Bsm[kk][tx*4];
#pragma unroll
            for (int r = 0; r < 8; r++) {
                float av = As[ty*8 + r][kk];
                acc[r][0] += av*bv.x; acc[r][1] += av*bv.y;
                acc[r][2] += av*bv.z; acc[r][3] += av*bv.w;
            }
        }
        __syncthreads();
    }
#pragma unroll
    for (int r = 0; r < 8; r++) {
        *(float4*)&g_Wh[(size_t)(block_row + ty*8 + r)*FOUT + tx*4] =
            make_float4(acc[r][0], acc[r][1], acc[r][2], acc[r][3]);
    }
}

// ============ Kernel 2: Wh1 = Wh·a1, Wh2 = Wh·a2 ============
__global__ void __launch_bounds__(256) k_rowvec(const float* __restrict__ a) {
    int warp = (blockIdx.x * blockDim.x + threadIdx.x) >> 5;
    int lane = threadIdx.x & 31;
    if (warp >= ROWS) return;
    const float* wr = g_Wh + (size_t)warp*FOUT;
    float s1 = 0.f, s2 = 0.f;
#pragma unroll
    for (int j = 0; j < 4; j++) {
        int o = lane + 32*j;
        float v = wr[o];
        s1 += v * a[o];
        s2 += v * a[FOUT + o];
    }
#pragma unroll
    for (int off = 16; off; off >>= 1) {
        s1 += __shfl_xor_sync(0xffffffffu, s1, off);
        s2 += __shfl_xor_sync(0xffffffffu, s2, off);
    }
    if (lane == 0) { g_Wh1[warp] = s1; g_Wh2[warp] = s2; }
}

// ==== Kernel 3: gather Wh rows in pi order -> WhB [b][f][k], pair-permuted; also Wh2p ====
__global__ void __launch_bounds__(128) k_trans() {
    __shared__ float ts[32*128];   // [l][f]
    const int cp = blockIdx.x, b = blockIdx.y, tid = threadIdx.x;
    const int mbase = (cp >> 2) << 7, moff = cp & 3;
#pragma unroll
    for (int i = 0; i < 8; i++) {
        int idx = tid + 128*i;          // float4 index, 1024 total
        int l = idx >> 5, f4 = idx & 31;
        int m = mbase + 4*l + moff;
        ((float4*)ts)[idx] = *(((const float4*)(g_Wh + (size_t)(b*NN + m)*FOUT)) + f4);
    }
    if (tid < 32)
        g_Wh2p[b*NN + cp*32 + tid] = g_Wh2[b*NN + mbase + 4*tid + moff];
    __syncthreads();
    const int f = tid;
    float* dst = g_WhB + ((size_t)b*FOUT + f)*NN + cp*32;
#pragma unroll
    for (int s = 0; s < 4; s++)
#pragma unroll
        for (int t = 0; t < 4; t++) {
            float2 v;
            v.x = to_tf32(ts[(s*8 + t    )*128 + f]);
            v.y = to_tf32(ts[(s*8 + t + 4)*128 + f]);
            *(float2*)(dst + s*8 + 2*t) = v;
        }
}

// ==== Kernel 4: one pass over adj (int4): pack pi-ordered mask + softmax denom ====
__global__ void __launch_bounds__(256) k_stats(const int* __restrict__ adj) {
    int warp = (blockIdx.x * blockDim.x + threadIdx.x) >> 5;
    int lane = threadIdx.x & 31;
    if (warp >= ROWS) return;
    const int row = warp, b = row >> 12, n = row & (NN-1);
    const float w1 = g_Wh1[row];
    const int4*   arow = (const int4*)(adj + (size_t)row * NN);
    const float4* w2   = (const float4*)(g_Wh2 + (size_t)b * NN);
    unsigned* mbase = g_maskT + (size_t)b*NCH*NN + n;
    float sum = 0.f;
#pragma unroll 4
    for (int g = 0; g < 32; g++) {
        int4   av = arow[g*32 + lane];
        float4 ev = w2[g*32 + lane];
        float e0 = w1 + ev.x; e0 = (e0>=0.f)?e0:0.2f*e0;
        float e1 = w1 + ev.y; e1 = (e1>=0.f)?e1:0.2f*e1;
        float e2 = w1 + ev.z; e2 = (e2>=0.f)?e2:0.2f*e2;
        float e3 = w1 + ev.w; e3 = (e3>=0.f)?e3:0.2f*e3;
        unsigned b0 = __ballot_sync(0xffffffffu, av.x > 0);
        unsigned b1 = __ballot_sync(0xffffffffu, av.y > 0);
        unsigned b2 = __ballot_sync(0xffffffffu, av.z > 0);
        unsigned b3 = __ballot_sync(0xffffffffu, av.w > 0);
        if (av.x > 0) sum += __expf(e0);
        if (av.y > 0) sum += __expf(e1);
        if (av.z > 0) sum += __expf(e2);
        if (av.w > 0) sum += __expf(e3);
        if (lane < 4) {
            unsigned bb = (lane == 0) ? b0 : (lane == 1) ? b1 : (lane == 2) ? b2 : b3;
            mbase[(size_t)(g*4 + lane) * NN] = bb;
        }
    }
#pragma unroll
    for (int off = 16; off; off >>= 1) sum += __shfl_xor_sync(0xffffffffu, sum, off);
    if (lane == 0) g_invZ[row] = 1.f / sum;
}

// ============ Kernel 5: h' = attn @ Wh via mma.sync tf32, pipelined ============
// 512 threads (16 warps: 4M x 4N, warp tile 32x32). cp.async 3-stage W ring,
// 2-stage P ring, ONE __syncthreads per chunk.
__global__ void __launch_bounds__(512) k_pv(float* __restrict__ out) {
    __shared__ float Ws[3][128*PSTR];   // 60 KB  Wh^T tiles (gmem layout already permuted)
    __shared__ float Ps[2][128*PSTR];   // 40 KB  P tiles

    const int b   = blockIdx.y;
    const int n0  = blockIdx.x * 128;
    const int tid = threadIdx.x;
    const int warp = tid >> 5, lane = tid & 31;
    const int g = lane >> 2, t = lane & 3;
    const int mband = (warp >> 2) * 32;
    const int nband = (warp & 3) * 32;

    // P-producer role: row + one s-group of 8 k-positions
    const int mrow = tid >> 2;
    const int kq   = (tid & 3) * 8;
    const float w1 = g_Wh1[b*NN + n0 + mrow];
    const float iz = g_invZ[b*NN + n0 + mrow];
    const unsigned* maskrow = g_maskT + (size_t)b*NCH*NN + n0 + mrow;
    const float*    wh2p    = g_Wh2p + b*NN + kq;

    // W copy role: 2 x 16B lines per thread per chunk
    const int wL0 = tid * 2;
    const int wn0 = wL0 >> 3, wp0 = (wL0 & 7) * 4;
    const int wn1 = (wL0+1) >> 3, wp1 = ((wL0+1) & 7) * 4;
    const float* gWb = g_WhB + (size_t)b*FOUT*NN;
    const uint32_t wsBase = smem_u32(&Ws[0][0]);

    float acc[2][4][4];
#pragma unroll
    for (int mf = 0; mf < 2; mf++)
#pragma unroll
        for (int nf = 0; nf < 4; nf++)
#pragma unroll
            for (int i = 0; i < 4; i++) acc[mf][nf][i] = 0.f;

    // ---- prologue: issue W0, W1 ----
#pragma unroll
    for (int c = 0; c < 2; c++) {
        uint32_t ds = wsBase + (uint32_t)(c)*(128*PSTR*4);
        cp_async16(ds + (wn0*PSTR + wp0)*4, gWb + (size_t)wn0*NN + c*32 + wp0);
        cp_async16(ds + (wn1*PSTR + wp1)*4, gWb + (size_t)wn1*NN + c*32 + wp1);
        CP_COMMIT();
    }
    // P inputs for c=0, prefetch c=1
    unsigned mw   = maskrow[0];
    float4 w2a    = *(const float4*)(wh2p + 0);
    float4 w2b    = *(const float4*)(wh2p + 4);
    unsigned mw_n = maskrow[NN];
    float4 w2a_n  = *(const float4*)(wh2p + 32);
    float4 w2b_n  = *(const float4*)(wh2p + 36);

    // compute P(0) -> Ps[0]
    {
        float* pd = &Ps[0][mrow*PSTR + kq];
        float pa[4], pb[4];
#pragma unroll
        for (int tt = 0; tt < 4; tt++) {
            float e0 = w1 + ((const float*)&w2a)[tt]; e0 = (e0>=0.f)?e0:0.2f*e0;
            float e1 = w1 + ((const float*)&w2b)[tt]; e1 = (e1>=0.f)?e1:0.2f*e1;
            pa[tt] = ((mw >> (kq+tt))   & 1u) ? to_tf32(__expf(e0)*iz) : 0.f;
            pb[tt] = ((mw >> (kq+tt+4)) & 1u) ? to_tf32(__expf(e1)*iz) : 0.f;
        }
        *(float4*)(pd)   = make_float4(pa[0], pb[0], pa[1], pb[1]);
        *(float4*)(pd+4) = make_float4(pa[2], pb[2], pa[3], pb[3]);
    }
    mw = mw_n; w2a = w2a_n; w2b = w2b_n;
    mw_n  = maskrow[2*(size_t)NN];
    w2a_n = *(const float4*)(wh2p + 64);
    w2b_n = *(const float4*)(wh2p + 68);

    for (int c = 0; c < NCH; c++) {
        CP_WAIT1();
        __syncthreads();

        // issue W(c+2) into slot (c+2)%3; always commit to keep group count regular
        if (c + 2 < NCH) {
            uint32_t ds = wsBase + (uint32_t)((c+2)%3)*(128*PSTR*4);
            cp_async16(ds + (wn0*PSTR + wp0)*4, gWb + (size_t)wn0*NN + (c+2)*32 + wp0);
            cp_async16(ds + (wn1*PSTR + wp1)*4, gWb + (size_t)wn1*NN + (c+2)*32 + wp1);
        }
        CP_COMMIT();

        // compute P(c+1) -> Ps[(c+1)&1]; prefetch inputs for c+2
        if (c + 1 < NCH) {
            float* pd = &Ps[(c+1)&1][mrow*PSTR + kq];
            float pa[4], pb[4];
#pragma unroll
            for (int tt = 0; tt < 4; tt++) {
                float e0 = w1 + ((const float*)&w2a)[tt]; e0 = (e0>=0.f)?e0:0.2f*e0;
                float e1 = w1 + ((const float*)&w2b)[tt]; e1 = (e1>=0.f)?e1:0.2f*e1;
                pa[tt] = ((mw >> (kq+tt))   & 1u) ? to_tf32(__expf(e0)*iz) : 0.f;
                pb[tt] = ((mw >> (kq+tt+4)) & 1u) ? to_tf32(__expf(e1)*iz) : 0.f;
            }
            *(float4*)(pd)   = make_float4(pa[0], pb[0], pa[1], pb[1]);
            *(float4*)(pd+4) = make_float4(pa[2], pb[2], pa[3], pb[3]);
            mw = mw_n; w2a = w2a_n; w2b = w2b_n;
            if (c + 3 < NCH) {
                mw_n  = maskrow[(size_t)(c+3)*NN];
                w2a_n = *(const float4*)(wh2p + (c+3)*32);
                w2b_n = *(const float4*)(wh2p + (c+3)*32 + 4);
            }
        }

        // MMA(c)
        const float* ws = Ws[c % 3];
        const float* ps = Ps[c & 1];
#pragma unroll
        for (int ks = 0; ks < 4; ks++) {
            uint2 bf[4];
#pragma unroll
            for (int nf = 0; nf < 4; nf++)
                bf[nf] = *(const uint2*)&ws[(nband + nf*8 + g)*PSTR + ks*8 + 2*t];
#pragma unroll
            for (int mf = 0; mf < 2; mf++) {
                uint2 aLo = *(const uint2*)&ps[(mband + mf*16 + g    )*PSTR + ks*8 + 2*t];
                uint2 aHi = *(const uint2*)&ps[(mband + mf*16 + g + 8)*PSTR + ks*8 + 2*t];
#pragma unroll
                for (int nf = 0; nf < 4; nf++)
                    mma_tf32(acc[mf][nf], aLo.x, aHi.x, aLo.y, aHi.y, bf[nf].x, bf[nf].y);
            }
        }
        __syncthreads();
    }

    // epilogue: ELU + store
#pragma unroll
    for (int mf = 0; mf < 2; mf++) {
        int r0 = b*NN + n0 + mband + mf*16 + g;
#pragma unroll
        for (int nf = 0; nf < 4; nf++) {
            int col = nband + nf*8 + t*2;
            float d0 = acc[mf][nf][0], d1 = acc[mf][nf][1];
            float d2 = acc[mf][nf][2], d3 = acc[mf][nf][3];
            d0 = (d0 > 0.f) ? d0 : expm1f(d0);
            d1 = (d1 > 0.f) ? d1 : expm1f(d1);
            d2 = (d2 > 0.f) ? d2 : expm1f(d2);
            d3 = (d3 > 0.f) ? d3 : expm1f(d3);
            *(float2*)&out[(size_t)r0*FOUT + col]     = make_float2(d0, d1);
            *(float2*)&out[(size_t)(r0+8)*FOUT + col] = make_float2(d2, d3);
        }
    }
}

extern "C" void kernel_launch(void* const* d_in, const int* in_sizes, int n_in,
                              void* d_out, int out_size) {
    const float* h   = (const float*)d_in[0];
    const int*   adj = (const int*)  d_in[1];
    const float* W   = (const float*)d_in[2];
    const float* a   = (const float*)d_in[3];
    float* out = (float*)d_out;

    k_gemm  <<<ROWS/64, 256>>>(h, W);
    k_rowvec<<<ROWS/8,  256>>>(a);
    { dim3 g(NCH, NB); k_trans<<<g, 128>>>(); }
    k_stats <<<ROWS/8,  256>>>(adj);
    { dim3 g(NN/128, NB); k_pv<<<g, 512>>>(out); }
}

// round 6
// speedup vs baseline: 2.0826x; 1.0001x over previous
#include <cuda_runtime.h>
#include <cstdint>

#define NB 4
#define NN 4096
#define FIN 256
#define FOUT 128
#define ROWS (NB*NN)
#define NCH 128            // 4096/32 k-chunks
#define PSTR 40            // smem row stride (words); 40 mod 32 = 8 -> conflict-free LDS.64

// -------- scratch (static __device__, no allocs) --------
__device__ float    g_Wh[(size_t)ROWS*FOUT];            // 8 MB   Wh row-major [row][f]
__device__ float    g_WhB[(size_t)NB*FOUT*NN];          // 8 MB   [b][f][k-pos] tf32 (pi-ordered, pair-permuted)
__device__ float    g_Wh1[ROWS];
__device__ float    g_Wh2[ROWS];
__device__ float    g_Wh2p[NB*NN];                      // Wh2 in pi order
__device__ float    g_invZ[ROWS];
__device__ unsigned g_maskT[(size_t)NB*NCH*NN];         // 8 MB   [b][chunk][n], bit l <-> m = pi(chunk,l)

// pi(c, l) = (c>>2)*128 + 4*l + (c&3)   -- matches int4-ballot order in k_stats

__device__ __forceinline__ float to_tf32(float x) {
    uint32_t b; asm("cvt.rna.tf32.f32 %0, %1;" : "=r"(b) : "f"(x));
    return __uint_as_float(b);
}
__device__ __forceinline__ void mma_tf32(float* d, uint32_t a0, uint32_t a1, uint32_t a2, uint32_t a3,
                                         uint32_t b0, uint32_t b1) {
    asm volatile("mma.sync.aligned.m16n8k8.row.col.f32.tf32.tf32.f32 "
                 "{%0,%1,%2,%3}, {%4,%5,%6,%7}, {%8,%9}, {%0,%1,%2,%3};"
                 : "+f"(d[0]), "+f"(d[1]), "+f"(d[2]), "+f"(d[3])
                 : "r"(a0), "r"(a1), "r"(a2), "r"(a3), "r"(b0), "r"(b1));
}
__device__ __forceinline__ uint32_t smem_u32(const void* p) {
    uint32_t a;
    asm("{ .reg .u64 t; cvta.to.shared.u64 t, %1; cvt.u32.u64 %0, t; }" : "=r"(a) : "l"(p));
    return a;
}
__device__ __forceinline__ void cp_async16(uint32_t dst, const void* src) {
    asm volatile("cp.async.ca.shared.global [%0], [%1], 16;" :: "r"(dst), "l"(src));
}
#define CP_COMMIT() asm volatile("cp.async.commit_group;" ::: "memory")
#define CP_WAIT1()  asm volatile("cp.async.wait_group 1;" ::: "memory")

// ================= Kernel 1: Wh = h @ W  (fp32 tiled GEMM) =================
__global__ void __launch_bounds__(256) k_gemm(const float* __restrict__ h,
                                              const float* __restrict__ W) {
    __shared__ float As[64][32];
    __shared__ float Bsm[32][FOUT];
    const int block_row = blockIdx.x * 64;
    const int tid = threadIdx.x;
    const int tx = tid & 31, ty = tid >> 5;
    float acc[8][4];
#pragma unroll
    for (int r = 0; r < 8; r++) { acc[r][0]=acc[r][1]=acc[r][2]=acc[r][3]=0.f; }
    for (int k0 = 0; k0 < FIN; k0 += 32) {
#pragma unroll
        for (int i = tid; i < 64*32; i += 256) {
            int r = i >> 5, c = i & 31;
            As[r][c] = h[(size_t)(block_row + r)*FIN + k0 + c];
        }
#pragma unroll
        for (int i = tid; i < 32*FOUT; i += 256) {
            int r = i >> 7, c = i & 127;
            Bsm[r][c] = W[(size_t)(k0 + r)*FOUT + c];
        }
        __syncthreads();
#pragma unroll
        for (int kk = 0; kk < 32; kk++) {
            float4 bv = *(const float4*)&Bsm[kk][tx*4];
#pragma unroll
            for (int r = 0; r < 8; r++) {
                float av = As[ty*8 + r][kk];
                acc[r][0] += av*bv.x; acc[r][1] += av*bv.y;
                acc[r][2] += av*bv.z; acc[r][3] += av*bv.w;
            }
        }
        __syncthreads();
    }
#pragma unroll
    for (int r = 0; r < 8; r++) {
        *(float4*)&g_Wh[(size_t)(block_row + ty*8 + r)*FOUT + tx*4] =
            make_float4(acc[r][0], acc[r][1], acc[r][2], acc[r][3]);
    }
}

// ============ Kernel 2: Wh1 = Wh·a1, Wh2 = Wh·a2 ============
__global__ void __launch_bounds__(256) k_rowvec(const float* __restrict__ a) {
    int warp = (blockIdx.x * blockDim.x + threadIdx.x) >> 5;
    int lane = threadIdx.x & 31;
    if (warp >= ROWS) return;
    const float* wr = g_Wh + (size_t)warp*FOUT;
    float s1 = 0.f, s2 = 0.f;
#pragma unroll
    for (int j = 0; j < 4; j++) {
        int o = lane + 32*j;
        float v = wr[o];
        s1 += v * a[o];
        s2 += v * a[FOUT + o];
    }
#pragma unroll
    for (int off = 16; off; off >>= 1) {
        s1 += __shfl_xor_sync(0xffffffffu, s1, off);
        s2 += __shfl_xor_sync(0xffffffffu, s2, off);
    }
    if (lane == 0) { g_Wh1[warp] = s1; g_Wh2[warp] = s2; }
}

// ==== Kernel 3: gather Wh rows in pi order -> WhB [b][f][k], pair-permuted; also Wh2p ====
__global__ void __launch_bounds__(128) k_trans() {
    __shared__ float ts[32*128];   // [l][f]
    const int cp = blockIdx.x, b = blockIdx.y, tid = threadIdx.x;
    const int mbase = (cp >> 2) << 7, moff = cp & 3;
#pragma unroll
    for (int i = 0; i < 8; i++) {
        int idx = tid + 128*i;          // float4 index, 1024 total
        int l = idx >> 5, f4 = idx & 31;
        int m = mbase + 4*l + moff;
        ((float4*)ts)[idx] = *(((const float4*)(g_Wh + (size_t)(b*NN + m)*FOUT)) + f4);
    }
    if (tid < 32)
        g_Wh2p[b*NN + cp*32 + tid] = g_Wh2[b*NN + mbase + 4*tid + moff];
    __syncthreads();
    const int f = tid;
    float* dst = g_WhB + ((size_t)b*FOUT + f)*NN + cp*32;
#pragma unroll
    for (int s = 0; s < 4; s++)
#pragma unroll
        for (int t = 0; t < 4; t++) {
            float2 v;
            v.x = to_tf32(ts[(s*8 + t    )*128 + f]);
            v.y = to_tf32(ts[(s*8 + t + 4)*128 + f]);
            *(float2*)(dst + s*8 + 2*t) = v;
        }
}

// ==== Kernel 4: one pass over adj (int4): pack pi-ordered mask + softmax denom ====
__global__ void __launch_bounds__(256) k_stats(const int* __restrict__ adj) {
    int warp = (blockIdx.x * blockDim.x + threadIdx.x) >> 5;
    int lane = threadIdx.x & 31;
    if (warp >= ROWS) return;
    const int row = warp, b = row >> 12, n = row & (NN-1);
    const float w1 = g_Wh1[row];
    const int4*   arow = (const int4*)(adj + (size_t)row * NN);
    const float4* w2   = (const float4*)(g_Wh2 + (size_t)b * NN);
    unsigned* mbase = g_maskT + (size_t)b*NCH*NN + n;
    float sum = 0.f;
#pragma unroll 4
    for (int g = 0; g < 32; g++) {
        int4   av = arow[g*32 + lane];
        float4 ev = w2[g*32 + lane];
        float e0 = w1 + ev.x; e0 = (e0>=0.f)?e0:0.2f*e0;
        float e1 = w1 + ev.y; e1 = (e1>=0.f)?e1:0.2f*e1;
        float e2 = w1 + ev.z; e2 = (e2>=0.f)?e2:0.2f*e2;
        float e3 = w1 + ev.w; e3 = (e3>=0.f)?e3:0.2f*e3;
        unsigned b0 = __ballot_sync(0xffffffffu, av.x > 0);
        unsigned b1 = __ballot_sync(0xffffffffu, av.y > 0);
        unsigned b2 = __ballot_sync(0xffffffffu, av.z > 0);
        unsigned b3 = __ballot_sync(0xffffffffu, av.w > 0);
        if (av.x > 0) sum += __expf(e0);
        if (av.y > 0) sum += __expf(e1);
        if (av.z > 0) sum += __expf(e2);
        if (av.w > 0) sum += __expf(e3);
        if (lane < 4) {
            unsigned bb = (lane == 0) ? b0 : (lane == 1) ? b1 : (lane == 2) ? b2 : b3;
            mbase[(size_t)(g*4 + lane) * NN] = bb;
        }
    }
#pragma unroll
    for (int off = 16; off; off >>= 1) sum += __shfl_xor_sync(0xffffffffu, sum, off);
    if (lane == 0) g_invZ[row] = 1.f / sum;
}

// ============ Kernel 5: h' = attn @ Wh via mma.sync tf32, pipelined ============
// 512 threads (16 warps: 4M x 4N, warp tile 32x32). cp.async 3-stage W ring,
// 2-stage P ring, ONE __syncthreads per chunk.
__global__ void __launch_bounds__(512) k_pv(float* __restrict__ out) {
    __shared__ float Ws[3][128*PSTR];   // 60 KB  Wh^T tiles (gmem layout already permuted)
    __shared__ float Ps[2][128*PSTR];   // 40 KB  P tiles

    const int b   = blockIdx.y;
    const int n0  = blockIdx.x * 128;
    const int tid = threadIdx.x;
    const int warp = tid >> 5, lane = tid & 31;
    const int g = lane >> 2, t = lane & 3;
    const int mband = (warp >> 2) * 32;
    const int nband = (warp & 3) * 32;

    // P-producer role: row + one s-group of 8 k-positions
    const int mrow = tid >> 2;
    const int kq   = (tid & 3) * 8;
    const float w1 = g_Wh1[b*NN + n0 + mrow];
    const float iz = g_invZ[b*NN + n0 + mrow];
    const unsigned* maskrow = g_maskT + (size_t)b*NCH*NN + n0 + mrow;
    const float*    wh2p    = g_Wh2p + b*NN + kq;

    // W copy role: 2 x 16B lines per thread per chunk
    const int wL0 = tid * 2;
    const int wn0 = wL0 >> 3, wp0 = (wL0 & 7) * 4;
    const int wn1 = (wL0+1) >> 3, wp1 = ((wL0+1) & 7) * 4;
    const float* gWb = g_WhB + (size_t)b*FOUT*NN;
    const uint32_t wsBase = smem_u32(&Ws[0][0]);

    float acc[2][4][4];
#pragma unroll
    for (int mf = 0; mf < 2; mf++)
#pragma unroll
        for (int nf = 0; nf < 4; nf++)
#pragma unroll
            for (int i = 0; i < 4; i++) acc[mf][nf][i] = 0.f;

    // ---- prologue: issue W0, W1 ----
#pragma unroll
    for (int c = 0; c < 2; c++) {
        uint32_t ds = wsBase + (uint32_t)(c)*(128*PSTR*4);
        cp_async16(ds + (wn0*PSTR + wp0)*4, gWb + (size_t)wn0*NN + c*32 + wp0);
        cp_async16(ds + (wn1*PSTR + wp1)*4, gWb + (size_t)wn1*NN + c*32 + wp1);
        CP_COMMIT();
    }
    // P inputs for c=0, prefetch c=1
    unsigned mw   = maskrow[0];
    float4 w2a    = *(const float4*)(wh2p + 0);
    float4 w2b    = *(const float4*)(wh2p + 4);
    unsigned mw_n = maskrow[NN];
    float4 w2a_n  = *(const float4*)(wh2p + 32);
    float4 w2b_n  = *(const float4*)(wh2p + 36);

    // compute P(0) -> Ps[0]
    {
        float* pd = &Ps[0][mrow*PSTR + kq];
        float pa[4], pb[4];
#pragma unroll
        for (int tt = 0; tt < 4; tt++) {
            float e0 = w1 + ((const float*)&w2a)[tt]; e0 = (e0>=0.f)?e0:0.2f*e0;
            float e1 = w1 + ((const float*)&w2b)[tt]; e1 = (e1>=0.f)?e1:0.2f*e1;
            pa[tt] = ((mw >> (kq+tt))   & 1u) ? to_tf32(__expf(e0)*iz) : 0.f;
            pb[tt] = ((mw >> (kq+tt+4)) & 1u) ? to_tf32(__expf(e1)*iz) : 0.f;
        }
        *(float4*)(pd)   = make_float4(pa[0], pb[0], pa[1], pb[1]);
        *(float4*)(pd+4) = make_float4(pa[2], pb[2], pa[3], pb[3]);
    }
    mw = mw_n; w2a = w2a_n; w2b = w2b_n;
    mw_n  = maskrow[2*(size_t)NN];
    w2a_n = *(const float4*)(wh2p + 64);
    w2b_n = *(const float4*)(wh2p + 68);

    for (int c = 0; c < NCH; c++) {
        CP_WAIT1();
        __syncthreads();

        // issue W(c+2) into slot (c+2)%3; always commit to keep group count regular
        if (c + 2 < NCH) {
            uint32_t ds = wsBase + (uint32_t)((c+2)%3)*(128*PSTR*4);
            cp_async16(ds + (wn0*PSTR + wp0)*4, gWb + (size_t)wn0*NN + (c+2)*32 + wp0);
            cp_async16(ds + (wn1*PSTR + wp1)*4, gWb + (size_t)wn1*NN + (c+2)*32 + wp1);
        }
        CP_COMMIT();

        // compute P(c+1) -> Ps[(c+1)&1]; prefetch inputs for c+2
        if (c + 1 < NCH) {
            float* pd = &Ps[(c+1)&1][mrow*PSTR + kq];
            float pa[4], pb[4];
#pragma unroll
            for (int tt = 0; tt < 4; tt++) {
                float e0 = w1 + ((const float*)&w2a)[tt]; e0 = (e0>=0.f)?e0:0.2f*e0;
                float e1 = w1 + ((const float*)&w2b)[tt]; e1 = (e1>=0.f)?e1:0.2f*e1;
                pa[tt] = ((mw >> (kq+tt))   & 1u) ? to_tf32(__expf(e0)*iz) : 0.f;
                pb[tt] = ((mw >> (kq+tt+4)) & 1u) ? to_tf32(__expf(e1)*iz) : 0.f;
            }
            *(float4*)(pd)   = make_float4(pa[0], pb[0], pa[1], pb[1]);
            *(float4*)(pd+4) = make_float4(pa[2], pb[2], pa[3], pb[3]);
            mw = mw_n; w2a = w2a_n; w2b = w2b_n;
            if (c + 3 < NCH) {
                mw_n  = maskrow[(size_t)(c+3)*NN];
                w2a_n = *(const float4*)(wh2p + (c+3)*32);
                w2b_n = *(const float4*)(wh2p + (c+3)*32 + 4);
            }
        }

        // MMA(c)
        const float* ws = Ws[c % 3];
        const float* ps = Ps[c & 1];
#pragma unroll
        for (int ks = 0; ks < 4; ks++) {
            uint2 bf[4];
#pragma unroll
            for (int nf = 0; nf < 4; nf++)
                bf[nf] = *(const uint2*)&ws[(nband + nf*8 + g)*PSTR + ks*8 + 2*t];
#pragma unroll
            for (int mf = 0; mf < 2; mf++) {
                uint2 aLo = *(const uint2*)&ps[(mband + mf*16 + g    )*PSTR + ks*8 + 2*t];
                uint2 aHi = *(const uint2*)&ps[(mband + mf*16 + g + 8)*PSTR + ks*8 + 2*t];
#pragma unroll
                for (int nf = 0; nf < 4; nf++)
                    mma_tf32(acc[mf][nf], aLo.x, aHi.x, aLo.y, aHi.y, bf[nf].x, bf[nf].y);
            }
        }
        __syncthreads();
    }

    // epilogue: ELU + store
#pragma unroll
    for (int mf = 0; mf < 2; mf++) {
        int r0 = b*NN + n0 + mband + mf*16 + g;
#pragma unroll
        for (int nf = 0; nf < 4; nf++) {
            int col = nband + nf*8 + t*2;
            float d0 = acc[mf][nf][0], d1 = acc[mf][nf][1];
            float d2 = acc[mf][nf][2], d3 = acc[mf][nf][3];
            d0 = (d0 > 0.f) ? d0 : expm1f(d0);
            d1 = (d1 > 0.f) ? d1 : expm1f(d1);
            d2 = (d2 > 0.f) ? d2 : expm1f(d2);
            d3 = (d3 > 0.f) ? d3 : expm1f(d3);
            *(float2*)&out[(size_t)r0*FOUT + col]     = make_float2(d0, d1);
            *(float2*)&out[(size_t)(r0+8)*FOUT + col] = make_float2(d2, d3);
        }
    }
}

extern "C" void kernel_launch(void* const* d_in, const int* in_sizes, int n_in,
                              void* d_out, int out_size) {
    const float* h   = (const float*)d_in[0];
    const int*   adj = (const int*)  d_in[1];
    const float* W   = (const float*)d_in[2];
    const float* a   = (const float*)d_in[3];
    float* out = (float*)d_out;

    k_gemm  <<<ROWS/64, 256>>>(h, W);
    k_rowvec<<<ROWS/8,  256>>>(a);
    { dim3 g(NCH, NB); k_trans<<<g, 128>>>(); }
    k_stats <<<ROWS/8,  256>>>(adj);
    { dim3 g(NN/128, NB); k_pv<<<g, 512>>>(out); }
}